// round 13
// baseline (speedup 1.0000x reference)
#include <cuda_runtime.h>
#include <cuda_fp16.h>
#include <math.h>
#include <cstdint>

#define N_NODES 50000
#define F       128
#define NCLS    2
#define N_TILES ((N_NODES + 127) / 128)   // 391
#define BUCKET  64                         // slots per node (Poisson(16) safe)
#define GRID_G  148                        // persistent CTAs (1/SM, co-resident)

// Scratch (device globals: allocation-free; zero-initialized at load)
__device__ __half g_feat16[N_NODES * F];          // 12.8 MB
__device__ __half g_agg16[N_NODES * F];           // 12.8 MB (mean, scaled)
__device__ int    g_cnt[N_NODES];                 // zeroed by gather phase
__device__ int    g_bucket[N_NODES * BUCKET];     // 12.8 MB
__device__ unsigned long long g_bar;              // grid barrier ticket counter

// ---------------------------------------------------------------------------
// 0) prep+fill: convert feat->fp16 (first: overlaps), probe dtype, bucket fill
// ---------------------------------------------------------------------------
__global__ void prep_fill_kernel(const float* __restrict__ feat,
                                 const void* __restrict__ srcv,
                                 const void* __restrict__ dstv, int E) {
    __shared__ int s_nz;
    int tid = threadIdx.x;
    if (tid == 0) s_nz = 0;
    __syncthreads();
    if (tid < 64) {                        // per-block dtype probe (L2-cached)
        const int* s32 = (const int*)srcv;
        const int* d32 = (const int*)dstv;
        int lim = 2 * E < 128 ? 2 * E : 128;
        int i = 2 * tid + 1;
        if (i < lim && (s32[i] | d32[i])) atomicOr(&s_nz, 1);
    }
    __syncthreads();
    const int is64 = (s_nz == 0);          // all odd 32b words zero => int64

    int gtid = blockIdx.x * blockDim.x + tid;
    int stride = gridDim.x * blockDim.x;

    // feat -> fp16 first: DRAM-bound loads issue early, overlap atomics below
    const int NH4 = N_NODES * F / 4;
    const float4* f4 = (const float4*)feat;
    uint2* o2 = (uint2*)g_feat16;
    for (int i = gtid; i < NH4; i += stride) {
        float4 v = f4[i];
        __half2 h0 = __float22half2_rn(make_float2(v.x, v.y));
        __half2 h1 = __float22half2_rn(make_float2(v.z, v.w));
        uint2 o;
        o.x = *(uint32_t*)&h0;
        o.y = *(uint32_t*)&h1;
        o2[i] = o;
    }

    // edges: 4 per thread, batched loads -> batched atomics -> batched stores
    int nquad = (E + 3) >> 2;
    for (int qi = gtid; qi < nquad; qi += stride) {
        int base = qi * 4;
        int d[4], s[4];
        int cnt4 = (E - base) < 4 ? (E - base) : 4;
        if (cnt4 == 4) {
            if (is64) {
                const longlong2* dp = (const longlong2*)((const long long*)dstv + base);
                const longlong2* sp = (const longlong2*)((const long long*)srcv + base);
                longlong2 d01 = dp[0], d23 = dp[1];
                longlong2 s01 = sp[0], s23 = sp[1];
                d[0] = (int)d01.x; d[1] = (int)d01.y;
                d[2] = (int)d23.x; d[3] = (int)d23.y;
                s[0] = (int)s01.x; s[1] = (int)s01.y;
                s[2] = (int)s23.x; s[3] = (int)s23.y;
            } else {
                int4 dv = *(const int4*)((const int*)dstv + base);
                int4 sv = *(const int4*)((const int*)srcv + base);
                d[0] = dv.x; d[1] = dv.y; d[2] = dv.z; d[3] = dv.w;
                s[0] = sv.x; s[1] = sv.y; s[2] = sv.z; s[3] = sv.w;
            }
        } else {
            for (int j = 0; j < 4; j++) {
                if (j < cnt4) {
                    if (is64) {
                        d[j] = (int)reinterpret_cast<const long long*>(dstv)[base + j];
                        s[j] = (int)reinterpret_cast<const long long*>(srcv)[base + j];
                    } else {
                        d[j] = reinterpret_cast<const int*>(dstv)[base + j];
                        s[j] = reinterpret_cast<const int*>(srcv)[base + j];
                    }
                } else { d[j] = -1; s[j] = -1; }
            }
        }
        int pos[4];
        #pragma unroll
        for (int j = 0; j < 4; j++) {
            bool ok = (d[j] >= 0 && d[j] < N_NODES && s[j] >= 0 && s[j] < N_NODES);
            pos[j] = ok ? atomicAdd(&g_cnt[d[j]], 1) : BUCKET;
        }
        #pragma unroll
        for (int j = 0; j < 4; j++) {
            if (pos[j] < BUCKET)
                g_bucket[(size_t)d[j] * BUCKET + pos[j]] = s[j];
        }
    }
}

// ---------------------------------------------------------------------------
// 1) fused: gather-mean phase (full-grid parallel) -> grid barrier -> GEMM
// ---------------------------------------------------------------------------
#define RSTRIDE  528    // bytes per smem row (256 halves + 16B pad)
#define RWORDS   132    // u32 per row
#define A_BUF    67584  // 128 rows * 528 B
#define OFF_B    0
#define OFF_A    67584                    // 2 bufs -> 135168
#define OFF_BN   202752
#define OFF_F0   203264
#define OFF_F1   203776
#define OFF_PART 204288                   // [128][4][2] f32 = 4096 B
#define SMEM_TOTAL 208384

__device__ __forceinline__ uint32_t smem_u32(const void* p) {
    uint32_t a;
    asm("{ .reg .u64 t; cvta.to.shared.u64 t, %1; cvt.u32.u64 %0, t; }"
        : "=r"(a) : "l"(p));
    return a;
}
__device__ __forceinline__ void mma_f16(float* c, const uint32_t* a,
                                        const uint32_t* b) {
    asm volatile("mma.sync.aligned.m16n8k16.row.col.f32.f16.f16.f32 "
                 "{%0,%1,%2,%3}, {%4,%5,%6,%7}, {%8,%9}, {%0,%1,%2,%3};"
                 : "+f"(c[0]), "+f"(c[1]), "+f"(c[2]), "+f"(c[3])
                 : "r"(a[0]), "r"(a[1]), "r"(a[2]), "r"(a[3]),
                   "r"(b[0]), "r"(b[1]));
}
#define LDSM4(r, addr) \
    asm volatile("ldmatrix.sync.aligned.m8n8.x4.shared.b16 {%0,%1,%2,%3}, [%4];" \
                 : "=r"((r)[0]), "=r"((r)[1]), "=r"((r)[2]), "=r"((r)[3]) \
                 : "r"(addr))
#define CP_ASYNC16(dst, src) \
    asm volatile("cp.async.cg.shared.global [%0], [%1], 16;" \
                 :: "r"(dst), "l"(src) : "memory")
#define CP_COMMIT() asm volatile("cp.async.commit_group;" ::: "memory")
#define CP_WAIT0()  asm volatile("cp.async.wait_group 0;" ::: "memory")

__global__ void __launch_bounds__(512, 1)
fused_agg_gemm_kernel(const float* __restrict__ Wself,
                      const float* __restrict__ Wneigh,
                      const float* __restrict__ bneigh,
                      const float* __restrict__ Wfc,
                      const float* __restrict__ bfc,
                      float* __restrict__ out) {
    extern __shared__ char smem[];
    uint32_t* Bs = (uint32_t*)(smem + OFF_B);    // [n=128][k2=128]+pad
    float* bn_s  = (float*)(smem + OFF_BN);
    float* f0_s  = (float*)(smem + OFF_F0);
    float* f1_s  = (float*)(smem + OFF_F1);
    float* part  = (float*)(smem + OFF_PART);
    const uint32_t sbase = smem_u32(smem);
    const uint32_t sA = sbase + OFF_A;
    const uint32_t sB = sbase + OFF_B;

    const int tid = threadIdx.x;
    const int wid = tid >> 5, lane = tid & 31;
    const int m_idx = wid >> 2;          // 0..3: rows m_idx*32..+32
    const int n_idx = wid & 3;           // 0..3: cols n_idx*32..+32
    const int groupr = lane >> 2, tcol = lane & 3;

    // --- stage B = [Ws | Wn] as [n][k] fp16, once per CTA -------------------
    const float4* Ws4 = (const float4*)Wself;
    const float4* Wn4 = (const float4*)Wneigh;
    for (int t = tid; t < 128 * 64; t += 512) {
        int j  = t >> 6;                  // output col n (row of B)
        int kq = t & 63;                  // float4 index along combined K(256)
        float4 v = (kq < 32) ? Ws4[j * 32 + kq] : Wn4[j * 32 + (kq - 32)];
        __half2 h0 = __float22half2_rn(make_float2(v.x, v.y));
        __half2 h1 = __float22half2_rn(make_float2(v.z, v.w));
        uint2 o;
        o.x = *(uint32_t*)&h0;
        o.y = *(uint32_t*)&h1;
        *(uint2*)&Bs[j * RWORDS + kq * 2] = o;
    }
    if (tid < 128) {
        bn_s[tid] = bneigh[tid];
        f0_s[tid] = Wfc[tid];
        f1_s[tid] = Wfc[128 + tid];
    }

    // --- gather-mean phase: 4 nodes x 2-edge unroll per warp (8 rows in
    //     flight) over the full grid; writes g_agg16, zeroes g_cnt ----------
    {
        const uint2* f2 = (const uint2*)g_feat16;   // 32 uint2 per row
        const int gw = blockIdx.x * 16 + wid;       // 0..GRID_G*16-1
        const int NW = GRID_G * 16;
        for (int nb = gw * 4; nb < N_NODES; nb += NW * 4) {
            int n[4];
            const int* bk[4];
            float acc[4][4];
            int mx = 0;
            #pragma unroll
            for (int r = 0; r < 4; r++) {
                int node = nb + r;
                int nc = (node < N_NODES) ? node : 0;
                int deg = g_cnt[nc];
                n[r] = (node < N_NODES) ? (deg < BUCKET ? deg : BUCKET) : 0;
                bk[r] = &g_bucket[(size_t)nc * BUCKET];
                mx = n[r] > mx ? n[r] : mx;
                acc[r][0] = acc[r][1] = acc[r][2] = acc[r][3] = 0.f;
            }
            for (int e = 0; e < mx; e += 2) {
                #pragma unroll
                for (int r = 0; r < 4; r++) {
                    #pragma unroll
                    for (int j = 0; j < 2; j++) {
                        int idx = e + j;
                        if (idx < n[r]) {
                            int s0 = bk[r][idx];
                            uint2 u = f2[(size_t)s0 * 32 + lane];
                            float2 p0 = __half22float2(*(__half2*)&u.x);
                            float2 p1 = __half22float2(*(__half2*)&u.y);
                            acc[r][0] += p0.x; acc[r][1] += p0.y;
                            acc[r][2] += p1.x; acc[r][3] += p1.y;
                        }
                    }
                }
            }
            #pragma unroll
            for (int r = 0; r < 4; r++) {
                int node = nb + r;
                if (node < N_NODES) {
                    int deg = g_cnt[node];
                    float invd = __fdividef(1.0f, fmaxf((float)deg, 1.0f));
                    __half2 h0 = __float22half2_rn(
                        make_float2(acc[r][0] * invd, acc[r][1] * invd));
                    __half2 h1 = __float22half2_rn(
                        make_float2(acc[r][2] * invd, acc[r][3] * invd));
                    uint2 o;
                    o.x = *(uint32_t*)&h0;
                    o.y = *(uint32_t*)&h1;
                    ((uint2*)g_agg16)[(size_t)node * 32 + lane] = o;
                    if (lane == 0) g_cnt[node] = 0;   // restore invariant
                }
            }
        }
    }

    // --- software grid barrier (all GRID_G CTAs co-resident at 1/SM) -------
    __syncthreads();
    if (tid == 0) {
        __threadfence();
        unsigned long long t = atomicAdd(&g_bar, 1ULL);
        unsigned long long target = (t / GRID_G + 1ULL) * GRID_G;
        while (atomicAdd(&g_bar, 0ULL) < target) __nanosleep(64);
    }
    __syncthreads();
    __threadfence();

    const char* featb = (const char*)g_feat16;
    const char* aggb  = (const char*)g_agg16;
    const float bfc0 = bfc[0], bfc1 = bfc[1];

    // ldmatrix lane address components (bytes)
    const uint32_t aOff = (uint32_t)((m_idx * 32 + (lane & 15)) * RSTRIDE +
                                     (lane >> 4) * 16);
    const uint32_t bAddr0 = sB + (uint32_t)((n_idx * 32 + (lane & 7) +
                                             ((lane >> 4) & 1) * 8) * RSTRIDE +
                                            ((lane >> 3) & 1) * 16);

    // whole-tile A stager: 128 rows x 512 B (feat | agg), one commit group
    auto stage = [&](int tile, int bufi) {
        #pragma unroll
        for (int i = 0; i < 8; i++) {
            int idx = tid + i * 512;              // 0..4095
            int row = idx >> 5, q = idx & 31;     // 32 x 16B segs per row
            int node = tile * 128 + row;
            if (node >= N_NODES) node = N_NODES - 1;
            const char* src = (q < 16)
                ? featb + (size_t)node * 256 + q * 16
                : aggb  + (size_t)node * 256 + (q - 16) * 16;
            uint32_t dst = sA + bufi * A_BUF + row * RSTRIDE + q * 16;
            CP_ASYNC16(dst, src);
        }
        CP_COMMIT();
    };

    int buf = 0;
    int tile0 = blockIdx.x;
    if (tile0 < N_TILES) stage(tile0, 0);

    for (int tile = tile0; tile < N_TILES; tile += gridDim.x) {
        CP_WAIT0();
        __syncthreads();                  // A tile ready for all warps

        float C[2][4][4];
        #pragma unroll
        for (int mt = 0; mt < 2; mt++)
            #pragma unroll
            for (int nt = 0; nt < 4; nt++)
                #pragma unroll
                for (int i = 0; i < 4; i++) C[mt][nt][i] = 0.f;

        const uint32_t aBase = sA + buf * A_BUF + aOff;
        #pragma unroll
        for (int k = 0; k < 16; k++) {    // 16 k-steps of 16 halves
            uint32_t a0[4], a1[4], b0[4], b1[4];
            LDSM4(a0, aBase + k * 32);
            LDSM4(a1, aBase + 16 * RSTRIDE + k * 32);
            LDSM4(b0, bAddr0 + k * 32);
            LDSM4(b1, bAddr0 + 16 * RSTRIDE + k * 32);
            mma_f16(C[0][0], a0, b0);
            mma_f16(C[0][1], a0, b0 + 2);
            mma_f16(C[0][2], a0, b1);
            mma_f16(C[0][3], a0, b1 + 2);
            mma_f16(C[1][0], a1, b0);
            mma_f16(C[1][1], a1, b0 + 2);
            mma_f16(C[1][2], a1, b1);
            mma_f16(C[1][3], a1, b1 + 2);
        }
        __syncthreads();                  // all warps done reading buf

        int next = tile + gridDim.x;      // prefetch overlaps epilogue
        if (next < N_TILES) stage(next, buf ^ 1);

        // --- epilogue: h = relu(c + bn); p += h * fc; quad-reduce ----------
        float p[2][2][2];   // [mt][rowhalf][cls]
        #pragma unroll
        for (int mt = 0; mt < 2; mt++)
            #pragma unroll
            for (int hh = 0; hh < 2; hh++) { p[mt][hh][0] = 0.f; p[mt][hh][1] = 0.f; }

        #pragma unroll
        for (int nt = 0; nt < 4; nt++) {
            #pragma unroll
            for (int ii = 0; ii < 2; ii++) {
                int col = n_idx * 32 + nt * 8 + 2 * tcol + ii;
                float bnv = bn_s[col], f0v = f0_s[col], f1v = f1_s[col];
                #pragma unroll
                for (int mt = 0; mt < 2; mt++) {
                    #pragma unroll
                    for (int hh = 0; hh < 2; hh++) {
                        float h = fmaxf(C[mt][nt][hh * 2 + ii] + bnv, 0.f);
                        p[mt][hh][0] += h * f0v;
                        p[mt][hh][1] += h * f1v;
                    }
                }
            }
        }
        #pragma unroll
        for (int mt = 0; mt < 2; mt++)
            #pragma unroll
            for (int hh = 0; hh < 2; hh++)
                #pragma unroll
                for (int cl = 0; cl < 2; cl++) {
                    float v = p[mt][hh][cl];
                    v += __shfl_xor_sync(0xffffffffu, v, 1);
                    v += __shfl_xor_sync(0xffffffffu, v, 2);
                    p[mt][hh][cl] = v;
                }
        if (tcol == 0) {
            #pragma unroll
            for (int mt = 0; mt < 2; mt++)
                #pragma unroll
                for (int hh = 0; hh < 2; hh++) {
                    int row = m_idx * 32 + mt * 16 + hh * 8 + groupr;
                    part[row * 8 + n_idx * 2 + 0] = p[mt][hh][0];
                    part[row * 8 + n_idx * 2 + 1] = p[mt][hh][1];
                }
        }
        __syncthreads();
        if (tid < 128) {
            int node = tile * 128 + tid;
            if (node < N_NODES) {
                float l0 = part[tid * 8 + 0] + part[tid * 8 + 2] +
                           part[tid * 8 + 4] + part[tid * 8 + 6] + bfc0;
                float l1 = part[tid * 8 + 1] + part[tid * 8 + 3] +
                           part[tid * 8 + 5] + part[tid * 8 + 7] + bfc1;
                float2 o;
                o.x = 1.0f / (1.0f + expf(-l0));
                o.y = 1.0f / (1.0f + expf(-l1));
                *(float2*)&out[(size_t)node * 2] = o;
            }
        }
        buf ^= 1;
        // next tile's post-MMA __syncthreads orders part reuse
    }
}

// ---------------------------------------------------------------------------
extern "C" void kernel_launch(void* const* d_in, const int* in_sizes, int n_in,
                              void* d_out, int out_size) {
    const float* feat   = (const float*)d_in[0];
    const void*  src    = d_in[1];
    const void*  dst    = d_in[2];
    const float* Wself  = (const float*)d_in[3];
    const float* Wneigh = (const float*)d_in[4];
    const float* bneigh = (const float*)d_in[5];
    const float* Wfc    = (const float*)d_in[6];
    const float* bfc    = (const float*)d_in[7];
    float*       out    = (float*)d_out;
    int E = in_sizes[1];

    cudaFuncSetAttribute(fused_agg_gemm_kernel,
                         cudaFuncAttributeMaxDynamicSharedMemorySize, SMEM_TOTAL);

    prep_fill_kernel<<<740, 256>>>(feat, src, dst, E);
    fused_agg_gemm_kernel<<<GRID_G, 512, SMEM_TOTAL>>>(
        Wself, Wneigh, bneigh, Wfc, bfc, out);
}

// round 14
// speedup vs baseline: 1.5669x; 1.5669x over previous
#include <cuda_runtime.h>
#include <cuda_fp16.h>
#include <math.h>
#include <cstdint>

#define N_NODES 50000
#define F       128
#define NCLS    2
#define N_TILES ((N_NODES + 127) / 128)   // 391
#define BUCKET  64                         // slots per node (Poisson(16) safe)
#define GRID_P  592                        // 4 CTAs/SM, all co-resident

// Scratch (device globals: allocation-free; zero-initialized at load)
__device__ __half g_feat16[N_NODES * F];          // 12.8 MB
__device__ __half g_agg16[N_NODES * F];           // 12.8 MB (mean, scaled)
__device__ int    g_cnt[N_NODES];                 // zeroed by gather phase
__device__ int    g_bucket[N_NODES * BUCKET];     // 12.8 MB
__device__ unsigned long long g_bar;              // grid barrier ticket counter

// ---------------------------------------------------------------------------
// 0) fused prep+fill+aggregate (full occupancy, software grid barrier)
// ---------------------------------------------------------------------------
__global__ void __launch_bounds__(256, 4)
prep_agg_kernel(const float* __restrict__ feat,
                const void* __restrict__ srcv,
                const void* __restrict__ dstv, int E) {
    __shared__ int s_nz;
    int tid = threadIdx.x;
    if (tid == 0) s_nz = 0;
    __syncthreads();
    if (tid < 64) {                        // per-block dtype probe (L2-cached)
        const int* s32 = (const int*)srcv;
        const int* d32 = (const int*)dstv;
        int lim = 2 * E < 128 ? 2 * E : 128;
        int i = 2 * tid + 1;
        if (i < lim && (s32[i] | d32[i])) atomicOr(&s_nz, 1);
    }
    __syncthreads();
    const int is64 = (s_nz == 0);          // all odd 32b words zero => int64

    int gtid = blockIdx.x * blockDim.x + tid;
    int stride = gridDim.x * blockDim.x;

    // Phase A: conversion + edge fill, order by block parity for overlap
    auto do_convert = [&]() {
        const int NH4 = N_NODES * F / 4;
        const float4* f4 = (const float4*)feat;
        uint2* o2 = (uint2*)g_feat16;
        for (int i = gtid; i < NH4; i += stride) {
            float4 v = f4[i];
            __half2 h0 = __float22half2_rn(make_float2(v.x, v.y));
            __half2 h1 = __float22half2_rn(make_float2(v.z, v.w));
            uint2 o;
            o.x = *(uint32_t*)&h0;
            o.y = *(uint32_t*)&h1;
            o2[i] = o;
        }
    };
    auto do_fill = [&]() {
        for (int i = gtid; i < E; i += stride) {
            int d, s;
            if (is64) {
                d = (int)reinterpret_cast<const long long*>(dstv)[i];
                s = (int)reinterpret_cast<const long long*>(srcv)[i];
            } else {
                d = reinterpret_cast<const int*>(dstv)[i];
                s = reinterpret_cast<const int*>(srcv)[i];
            }
            if (d < 0 || d >= N_NODES || s < 0 || s >= N_NODES) continue;
            int pos = atomicAdd(&g_cnt[d], 1);
            if (pos < BUCKET) g_bucket[(size_t)d * BUCKET + pos] = s;
        }
    };
    if (blockIdx.x & 1) { do_fill(); do_convert(); }
    else                { do_convert(); do_fill(); }

    // --- software grid barrier (GRID_P CTAs co-resident at 4/SM) -----------
    __syncthreads();
    if (tid == 0) {
        __threadfence();
        unsigned long long t = atomicAdd(&g_bar, 1ULL);
        unsigned long long target = (t / GRID_P + 1ULL) * GRID_P;
        while (atomicAdd(&g_bar, 0ULL) < target) __nanosleep(64);
    }
    __syncthreads();
    __threadfence();

    // Phase B: gather-mean, warp per node (32 warps/SM resident)
    {
        int lane = tid & 31;
        int gw = blockIdx.x * 8 + (tid >> 5);      // 0..GRID_P*8-1
        const int NW = GRID_P * 8;                 // 4736 warps
        const uint2* f2 = (const uint2*)g_feat16;  // 32 uint2 per row
        for (int node = gw; node < N_NODES; node += NW) {
            int deg = g_cnt[node];
            int n = deg < BUCKET ? deg : BUCKET;
            const int* bk = &g_bucket[(size_t)node * BUCKET];
            float a0 = 0.f, a1 = 0.f, a2 = 0.f, a3 = 0.f;
            int e = 0;
            for (; e + 1 < n; e += 2) {
                int s0 = bk[e], s1 = bk[e + 1];
                uint2 u0 = f2[(size_t)s0 * 32 + lane];
                uint2 u1 = f2[(size_t)s1 * 32 + lane];
                float2 p0 = __half22float2(*(__half2*)&u0.x);
                float2 p1 = __half22float2(*(__half2*)&u0.y);
                float2 q0 = __half22float2(*(__half2*)&u1.x);
                float2 q1 = __half22float2(*(__half2*)&u1.y);
                a0 += p0.x + q0.x; a1 += p0.y + q0.y;
                a2 += p1.x + q1.x; a3 += p1.y + q1.y;
            }
            if (e < n) {
                int s0 = bk[e];
                uint2 u0 = f2[(size_t)s0 * 32 + lane];
                float2 p0 = __half22float2(*(__half2*)&u0.x);
                float2 p1 = __half22float2(*(__half2*)&u0.y);
                a0 += p0.x; a1 += p0.y; a2 += p1.x; a3 += p1.y;
            }
            float invd = __fdividef(1.0f, fmaxf((float)deg, 1.0f));
            __half2 h0 = __float22half2_rn(make_float2(a0 * invd, a1 * invd));
            __half2 h1 = __float22half2_rn(make_float2(a2 * invd, a3 * invd));
            uint2 o;
            o.x = *(uint32_t*)&h0;
            o.y = *(uint32_t*)&h1;
            ((uint2*)g_agg16)[(size_t)node * 32 + lane] = o;
            if (lane == 0) g_cnt[node] = 0;   // restore invariant
        }
    }
}

// ---------------------------------------------------------------------------
// 1) fp16 mma GEMM with ldmatrix fragments, one barrier per tile,
//    whole-tile cp.async double buffer, fused bias/relu/fc/sigmoid epilogue
// ---------------------------------------------------------------------------
#define RSTRIDE  528    // bytes per smem row (256 halves + 16B pad)
#define RWORDS   132    // u32 per row
#define A_BUF    67584  // 128 rows * 528 B
#define OFF_B    0
#define OFF_A    67584                    // 2 bufs -> 135168
#define OFF_BN   202752
#define OFF_F0   203264
#define OFF_F1   203776
#define OFF_PART 204288                   // [128][4][2] f32 = 4096 B
#define SMEM_TOTAL 208384

__device__ __forceinline__ uint32_t smem_u32(const void* p) {
    uint32_t a;
    asm("{ .reg .u64 t; cvta.to.shared.u64 t, %1; cvt.u32.u64 %0, t; }"
        : "=r"(a) : "l"(p));
    return a;
}
__device__ __forceinline__ void mma_f16(float* c, const uint32_t* a,
                                        const uint32_t* b) {
    asm volatile("mma.sync.aligned.m16n8k16.row.col.f32.f16.f16.f32 "
                 "{%0,%1,%2,%3}, {%4,%5,%6,%7}, {%8,%9}, {%0,%1,%2,%3};"
                 : "+f"(c[0]), "+f"(c[1]), "+f"(c[2]), "+f"(c[3])
                 : "r"(a[0]), "r"(a[1]), "r"(a[2]), "r"(a[3]),
                   "r"(b[0]), "r"(b[1]));
}
#define LDSM4(r, addr) \
    asm volatile("ldmatrix.sync.aligned.m8n8.x4.shared.b16 {%0,%1,%2,%3}, [%4];" \
                 : "=r"((r)[0]), "=r"((r)[1]), "=r"((r)[2]), "=r"((r)[3]) \
                 : "r"(addr))
#define CP_ASYNC16(dst, src) \
    asm volatile("cp.async.cg.shared.global [%0], [%1], 16;" \
                 :: "r"(dst), "l"(src) : "memory")
#define CP_COMMIT() asm volatile("cp.async.commit_group;" ::: "memory")
#define CP_WAIT0()  asm volatile("cp.async.wait_group 0;" ::: "memory")

__global__ void __launch_bounds__(512, 1)
mma_gemm_kernel(const float* __restrict__ Wself,
                const float* __restrict__ Wneigh,
                const float* __restrict__ bneigh,
                const float* __restrict__ Wfc,
                const float* __restrict__ bfc,
                float* __restrict__ out) {
    extern __shared__ char smem[];
    uint32_t* Bs = (uint32_t*)(smem + OFF_B);    // [n=128][k2=128]+pad
    float* bn_s  = (float*)(smem + OFF_BN);
    float* f0_s  = (float*)(smem + OFF_F0);
    float* f1_s  = (float*)(smem + OFF_F1);
    float* part  = (float*)(smem + OFF_PART);
    const uint32_t sbase = smem_u32(smem);
    const uint32_t sA = sbase + OFF_A;
    const uint32_t sB = sbase + OFF_B;

    const int tid = threadIdx.x;
    const int wid = tid >> 5, lane = tid & 31;
    const int m_idx = wid >> 2;          // 0..3: rows m_idx*32..+32
    const int n_idx = wid & 3;           // 0..3: cols n_idx*32..+32
    const int groupr = lane >> 2, tcol = lane & 3;

    // --- stage B = [Ws | Wn] as [n][k] fp16, once per CTA -------------------
    const float4* Ws4 = (const float4*)Wself;
    const float4* Wn4 = (const float4*)Wneigh;
    for (int t = tid; t < 128 * 64; t += 512) {
        int j  = t >> 6;                  // output col n (row of B)
        int kq = t & 63;                  // float4 index along combined K(256)
        float4 v = (kq < 32) ? Ws4[j * 32 + kq] : Wn4[j * 32 + (kq - 32)];
        __half2 h0 = __float22half2_rn(make_float2(v.x, v.y));
        __half2 h1 = __float22half2_rn(make_float2(v.z, v.w));
        uint2 o;
        o.x = *(uint32_t*)&h0;
        o.y = *(uint32_t*)&h1;
        *(uint2*)&Bs[j * RWORDS + kq * 2] = o;
    }
    if (tid < 128) {
        bn_s[tid] = bneigh[tid];
        f0_s[tid] = Wfc[tid];
        f1_s[tid] = Wfc[128 + tid];
    }

    const char* featb = (const char*)g_feat16;
    const char* aggb  = (const char*)g_agg16;
    const float bfc0 = bfc[0], bfc1 = bfc[1];

    // ldmatrix lane address components (bytes)
    const uint32_t aOff = (uint32_t)((m_idx * 32 + (lane & 15)) * RSTRIDE +
                                     (lane >> 4) * 16);
    const uint32_t bAddr0 = sB + (uint32_t)((n_idx * 32 + (lane & 7) +
                                             ((lane >> 4) & 1) * 8) * RSTRIDE +
                                            ((lane >> 3) & 1) * 16);

    // whole-tile A stager: 128 rows x 512 B (feat | agg), one commit group
    auto stage = [&](int tile, int bufi) {
        #pragma unroll
        for (int i = 0; i < 8; i++) {
            int idx = tid + i * 512;              // 0..4095
            int row = idx >> 5, q = idx & 31;     // 32 x 16B segs per row
            int node = tile * 128 + row;
            if (node >= N_NODES) node = N_NODES - 1;
            const char* src = (q < 16)
                ? featb + (size_t)node * 256 + q * 16
                : aggb  + (size_t)node * 256 + (q - 16) * 16;
            uint32_t dst = sA + bufi * A_BUF + row * RSTRIDE + q * 16;
            CP_ASYNC16(dst, src);
        }
        CP_COMMIT();
    };

    int buf = 0;
    int tile0 = blockIdx.x;
    if (tile0 < N_TILES) stage(tile0, 0);

    for (int tile = tile0; tile < N_TILES; tile += gridDim.x) {
        CP_WAIT0();
        __syncthreads();                  // A tile ready for all warps

        float C[2][4][4];
        #pragma unroll
        for (int mt = 0; mt < 2; mt++)
            #pragma unroll
            for (int nt = 0; nt < 4; nt++)
                #pragma unroll
                for (int i = 0; i < 4; i++) C[mt][nt][i] = 0.f;

        const uint32_t aBase = sA + buf * A_BUF + aOff;
        #pragma unroll
        for (int k = 0; k < 16; k++) {    // 16 k-steps of 16 halves
            uint32_t a0[4], a1[4], b0[4], b1[4];
            LDSM4(a0, aBase + k * 32);
            LDSM4(a1, aBase + 16 * RSTRIDE + k * 32);
            LDSM4(b0, bAddr0 + k * 32);
            LDSM4(b1, bAddr0 + 16 * RSTRIDE + k * 32);
            mma_f16(C[0][0], a0, b0);
            mma_f16(C[0][1], a0, b0 + 2);
            mma_f16(C[0][2], a0, b1);
            mma_f16(C[0][3], a0, b1 + 2);
            mma_f16(C[1][0], a1, b0);
            mma_f16(C[1][1], a1, b0 + 2);
            mma_f16(C[1][2], a1, b1);
            mma_f16(C[1][3], a1, b1 + 2);
        }
        __syncthreads();                  // all warps done reading buf

        int next = tile + gridDim.x;      // prefetch overlaps epilogue
        if (next < N_TILES) stage(next, buf ^ 1);

        // --- epilogue: h = relu(c + bn); p += h * fc; quad-reduce ----------
        float p[2][2][2];   // [mt][rowhalf][cls]
        #pragma unroll
        for (int mt = 0; mt < 2; mt++)
            #pragma unroll
            for (int hh = 0; hh < 2; hh++) { p[mt][hh][0] = 0.f; p[mt][hh][1] = 0.f; }

        #pragma unroll
        for (int nt = 0; nt < 4; nt++) {
            #pragma unroll
            for (int ii = 0; ii < 2; ii++) {
                int col = n_idx * 32 + nt * 8 + 2 * tcol + ii;
                float bnv = bn_s[col], f0v = f0_s[col], f1v = f1_s[col];
                #pragma unroll
                for (int mt = 0; mt < 2; mt++) {
                    #pragma unroll
                    for (int hh = 0; hh < 2; hh++) {
                        float h = fmaxf(C[mt][nt][hh * 2 + ii] + bnv, 0.f);
                        p[mt][hh][0] += h * f0v;
                        p[mt][hh][1] += h * f1v;
                    }
                }
            }
        }
        #pragma unroll
        for (int mt = 0; mt < 2; mt++)
            #pragma unroll
            for (int hh = 0; hh < 2; hh++)
                #pragma unroll
                for (int cl = 0; cl < 2; cl++) {
                    float v = p[mt][hh][cl];
                    v += __shfl_xor_sync(0xffffffffu, v, 1);
                    v += __shfl_xor_sync(0xffffffffu, v, 2);
                    p[mt][hh][cl] = v;
                }
        if (tcol == 0) {
            #pragma unroll
            for (int mt = 0; mt < 2; mt++)
                #pragma unroll
                for (int hh = 0; hh < 2; hh++) {
                    int row = m_idx * 32 + mt * 16 + hh * 8 + groupr;
                    part[row * 8 + n_idx * 2 + 0] = p[mt][hh][0];
                    part[row * 8 + n_idx * 2 + 1] = p[mt][hh][1];
                }
        }
        __syncthreads();
        if (tid < 128) {
            int node = tile * 128 + tid;
            if (node < N_NODES) {
                float l0 = part[tid * 8 + 0] + part[tid * 8 + 2] +
                           part[tid * 8 + 4] + part[tid * 8 + 6] + bfc0;
                float l1 = part[tid * 8 + 1] + part[tid * 8 + 3] +
                           part[tid * 8 + 5] + part[tid * 8 + 7] + bfc1;
                float2 o;
                o.x = 1.0f / (1.0f + expf(-l0));
                o.y = 1.0f / (1.0f + expf(-l1));
                *(float2*)&out[(size_t)node * 2] = o;
            }
        }
        buf ^= 1;
        // next tile's post-MMA __syncthreads orders part reuse
    }
}

// ---------------------------------------------------------------------------
extern "C" void kernel_launch(void* const* d_in, const int* in_sizes, int n_in,
                              void* d_out, int out_size) {
    const float* feat   = (const float*)d_in[0];
    const void*  src    = d_in[1];
    const void*  dst    = d_in[2];
    const float* Wself  = (const float*)d_in[3];
    const float* Wneigh = (const float*)d_in[4];
    const float* bneigh = (const float*)d_in[5];
    const float* Wfc    = (const float*)d_in[6];
    const float* bfc    = (const float*)d_in[7];
    float*       out    = (float*)d_out;
    int E = in_sizes[1];

    cudaFuncSetAttribute(mma_gemm_kernel,
                         cudaFuncAttributeMaxDynamicSharedMemorySize, SMEM_TOTAL);

    prep_agg_kernel<<<GRID_P, 256>>>(feat, src, dst, E);
    mma_gemm_kernel<<<148, 512, SMEM_TOTAL>>>(
        Wself, Wneigh, bneigh, Wfc, bfc, out);
}

// round 15
// speedup vs baseline: 1.8498x; 1.1805x over previous
#include <cuda_runtime.h>
#include <cuda_fp16.h>
#include <math.h>
#include <cstdint>

#define N_NODES 50000
#define F       128
#define NCLS    2
#define N_TILES ((N_NODES + 127) / 128)   // 391
#define BUCKET  64                         // slots per node (Poisson(16) safe)
#define FILL_BLOCKS 370
#define TOTAL_BLOCKS 740

// Scratch (device globals: allocation-free; zero-initialized at load)
__device__ __half g_feat16[N_NODES * F];          // 12.8 MB
__device__ __half g_agg16[N_NODES * F];           // 12.8 MB (mean, scaled)
__device__ int    g_cnt[N_NODES];                 // zeroed by aggregate tail
__device__ int    g_bucket[N_NODES * BUCKET];     // 12.8 MB

// ---------------------------------------------------------------------------
// 0) prep+fill with block-role split: fill blocks and convert blocks run
//    CONCURRENTLY (atomic-latency phase overlaps DRAM-BW phase)
// ---------------------------------------------------------------------------
__global__ void __launch_bounds__(256)
prep_fill_kernel(const float* __restrict__ feat,
                 const void* __restrict__ srcv,
                 const void* __restrict__ dstv, int E) {
    __shared__ int s_nz;
    int tid = threadIdx.x;
    if (tid == 0) s_nz = 0;
    __syncthreads();
    if (tid < 64) {                        // per-block dtype probe (L2-cached)
        const int* s32 = (const int*)srcv;
        const int* d32 = (const int*)dstv;
        int lim = 2 * E < 128 ? 2 * E : 128;
        int i = 2 * tid + 1;
        if (i < lim && (s32[i] | d32[i])) atomicOr(&s_nz, 1);
    }
    __syncthreads();
    const int is64 = (s_nz == 0);          // all odd 32b words zero => int64

    if (blockIdx.x < FILL_BLOCKS) {
        // edge fill: count + bucket append
        int gtid = blockIdx.x * 256 + tid;
        int stride = FILL_BLOCKS * 256;
        for (int i = gtid; i < E; i += stride) {
            int d, s;
            if (is64) {
                d = (int)reinterpret_cast<const long long*>(dstv)[i];
                s = (int)reinterpret_cast<const long long*>(srcv)[i];
            } else {
                d = reinterpret_cast<const int*>(dstv)[i];
                s = reinterpret_cast<const int*>(srcv)[i];
            }
            if (d < 0 || d >= N_NODES || s < 0 || s >= N_NODES) continue;
            int pos = atomicAdd(&g_cnt[d], 1);
            if (pos < BUCKET) g_bucket[(size_t)d * BUCKET + pos] = s;
        }
    } else {
        // feat -> fp16 conversion
        int gtid = (blockIdx.x - FILL_BLOCKS) * 256 + tid;
        int stride = (TOTAL_BLOCKS - FILL_BLOCKS) * 256;
        const int NH4 = N_NODES * F / 4;
        const float4* f4 = (const float4*)feat;
        uint2* o2 = (uint2*)g_feat16;
        for (int i = gtid; i < NH4; i += stride) {
            float4 v = f4[i];
            __half2 h0 = __float22half2_rn(make_float2(v.x, v.y));
            __half2 h1 = __float22half2_rn(make_float2(v.z, v.w));
            uint2 o;
            o.x = *(uint32_t*)&h0;
            o.y = *(uint32_t*)&h1;
            o2[i] = o;
        }
    }
}

// ---------------------------------------------------------------------------
// 1) aggregate: warp per node, fp16 gather, f32 accumulate, fp16 store;
//    zeroes g_cnt afterwards (invariant for next launch/graph replay)
// ---------------------------------------------------------------------------
__global__ void __launch_bounds__(256)
aggregate_kernel() {
    int warp = (blockIdx.x * blockDim.x + threadIdx.x) >> 5;
    int lane = threadIdx.x & 31;
    if (warp >= N_NODES) return;
    int deg = g_cnt[warp];
    int n = deg < BUCKET ? deg : BUCKET;
    const int* bk = &g_bucket[(size_t)warp * BUCKET];

    const uint2* f2 = (const uint2*)g_feat16;   // 32 uint2 per row (4 halves)
    float a0 = 0.f, a1 = 0.f, a2 = 0.f, a3 = 0.f;
    int e = 0;
    for (; e + 1 < n; e += 2) {
        int s0 = bk[e], s1 = bk[e + 1];
        uint2 u0 = f2[(size_t)s0 * 32 + lane];
        uint2 u1 = f2[(size_t)s1 * 32 + lane];
        float2 p0 = __half22float2(*(__half2*)&u0.x);
        float2 p1 = __half22float2(*(__half2*)&u0.y);
        float2 q0 = __half22float2(*(__half2*)&u1.x);
        float2 q1 = __half22float2(*(__half2*)&u1.y);
        a0 += p0.x + q0.x; a1 += p0.y + q0.y;
        a2 += p1.x + q1.x; a3 += p1.y + q1.y;
    }
    if (e < n) {
        int s0 = bk[e];
        uint2 u0 = f2[(size_t)s0 * 32 + lane];
        float2 p0 = __half22float2(*(__half2*)&u0.x);
        float2 p1 = __half22float2(*(__half2*)&u0.y);
        a0 += p0.x; a1 += p0.y; a2 += p1.x; a3 += p1.y;
    }
    float invd = __fdividef(1.0f, fmaxf((float)deg, 1.0f));
    __half2 h0 = __float22half2_rn(make_float2(a0 * invd, a1 * invd));
    __half2 h1 = __float22half2_rn(make_float2(a2 * invd, a3 * invd));
    uint2 o;
    o.x = *(uint32_t*)&h0;
    o.y = *(uint32_t*)&h1;
    ((uint2*)g_agg16)[(size_t)warp * 32 + lane] = o;
    if (lane == 0) g_cnt[warp] = 0;       // restore invariant for next call
}

// ---------------------------------------------------------------------------
// 2) fp16 mma GEMM with ldmatrix fragments; next-tile prefetch issued at the
//    TOP of each tile so the copy overlaps the whole MMA+epilogue
// ---------------------------------------------------------------------------
#define RSTRIDE  528    // bytes per smem row (256 halves + 16B pad)
#define RWORDS   132    // u32 per row
#define A_BUF    67584  // 128 rows * 528 B
#define OFF_B    0
#define OFF_A    67584                    // 2 bufs -> 135168
#define OFF_BN   202752
#define OFF_F0   203264
#define OFF_F1   203776
#define OFF_PART 204288                   // [128][4][2] f32 = 4096 B
#define SMEM_TOTAL 208384

__device__ __forceinline__ uint32_t smem_u32(const void* p) {
    uint32_t a;
    asm("{ .reg .u64 t; cvta.to.shared.u64 t, %1; cvt.u32.u64 %0, t; }"
        : "=r"(a) : "l"(p));
    return a;
}
__device__ __forceinline__ void mma_f16(float* c, const uint32_t* a,
                                        const uint32_t* b) {
    asm volatile("mma.sync.aligned.m16n8k16.row.col.f32.f16.f16.f32 "
                 "{%0,%1,%2,%3}, {%4,%5,%6,%7}, {%8,%9}, {%0,%1,%2,%3};"
                 : "+f"(c[0]), "+f"(c[1]), "+f"(c[2]), "+f"(c[3])
                 : "r"(a[0]), "r"(a[1]), "r"(a[2]), "r"(a[3]),
                   "r"(b[0]), "r"(b[1]));
}
#define LDSM4(r, addr) \
    asm volatile("ldmatrix.sync.aligned.m8n8.x4.shared.b16 {%0,%1,%2,%3}, [%4];" \
                 : "=r"((r)[0]), "=r"((r)[1]), "=r"((r)[2]), "=r"((r)[3]) \
                 : "r"(addr))
#define CP_ASYNC16(dst, src) \
    asm volatile("cp.async.cg.shared.global [%0], [%1], 16;" \
                 :: "r"(dst), "l"(src) : "memory")
#define CP_COMMIT() asm volatile("cp.async.commit_group;" ::: "memory")
#define CP_WAIT0()  asm volatile("cp.async.wait_group 0;" ::: "memory")

__global__ void __launch_bounds__(512, 1)
mma_gemm_kernel(const float* __restrict__ Wself,
                const float* __restrict__ Wneigh,
                const float* __restrict__ bneigh,
                const float* __restrict__ Wfc,
                const float* __restrict__ bfc,
                float* __restrict__ out) {
    extern __shared__ char smem[];
    uint32_t* Bs = (uint32_t*)(smem + OFF_B);    // [n=128][k2=128]+pad
    float* bn_s  = (float*)(smem + OFF_BN);
    float* f0_s  = (float*)(smem + OFF_F0);
    float* f1_s  = (float*)(smem + OFF_F1);
    float* part  = (float*)(smem + OFF_PART);
    const uint32_t sbase = smem_u32(smem);
    const uint32_t sA = sbase + OFF_A;
    const uint32_t sB = sbase + OFF_B;

    const int tid = threadIdx.x;
    const int wid = tid >> 5, lane = tid & 31;
    const int m_idx = wid >> 2;          // 0..3: rows m_idx*32..+32
    const int n_idx = wid & 3;           // 0..3: cols n_idx*32..+32
    const int groupr = lane >> 2, tcol = lane & 3;

    // --- stage B = [Ws | Wn] as [n][k] fp16, once per CTA -------------------
    const float4* Ws4 = (const float4*)Wself;
    const float4* Wn4 = (const float4*)Wneigh;
    for (int t = tid; t < 128 * 64; t += 512) {
        int j  = t >> 6;                  // output col n (row of B)
        int kq = t & 63;                  // float4 index along combined K(256)
        float4 v = (kq < 32) ? Ws4[j * 32 + kq] : Wn4[j * 32 + (kq - 32)];
        __half2 h0 = __float22half2_rn(make_float2(v.x, v.y));
        __half2 h1 = __float22half2_rn(make_float2(v.z, v.w));
        uint2 o;
        o.x = *(uint32_t*)&h0;
        o.y = *(uint32_t*)&h1;
        *(uint2*)&Bs[j * RWORDS + kq * 2] = o;
    }
    if (tid < 128) {
        bn_s[tid] = bneigh[tid];
        f0_s[tid] = Wfc[tid];
        f1_s[tid] = Wfc[128 + tid];
    }

    const char* featb = (const char*)g_feat16;
    const char* aggb  = (const char*)g_agg16;
    const float bfc0 = bfc[0], bfc1 = bfc[1];

    // ldmatrix lane address components (bytes)
    const uint32_t aOff = (uint32_t)((m_idx * 32 + (lane & 15)) * RSTRIDE +
                                     (lane >> 4) * 16);
    const uint32_t bAddr0 = sB + (uint32_t)((n_idx * 32 + (lane & 7) +
                                             ((lane >> 4) & 1) * 8) * RSTRIDE +
                                            ((lane >> 3) & 1) * 16);

    // whole-tile A stager: 128 rows x 512 B (feat | agg), one commit group
    auto stage = [&](int tile, int bufi) {
        #pragma unroll
        for (int i = 0; i < 8; i++) {
            int idx = tid + i * 512;              // 0..4095
            int row = idx >> 5, q = idx & 31;     // 32 x 16B segs per row
            int node = tile * 128 + row;
            if (node >= N_NODES) node = N_NODES - 1;
            const char* src = (q < 16)
                ? featb + (size_t)node * 256 + q * 16
                : aggb  + (size_t)node * 256 + (q - 16) * 16;
            uint32_t dst = sA + bufi * A_BUF + row * RSTRIDE + q * 16;
            CP_ASYNC16(dst, src);
        }
        CP_COMMIT();
    };

    int buf = 0;
    int tile0 = blockIdx.x;
    if (tile0 < N_TILES) stage(tile0, 0);

    for (int tile = tile0; tile < N_TILES; tile += gridDim.x) {
        CP_WAIT0();
        __syncthreads();                  // A tile (buf) ready for all warps

        // prefetch NEXT tile now: copy overlaps the whole MMA + epilogue.
        // buf^1 was fully consumed before the previous tile's post-MMA
        // barrier, so overwriting it here is safe.
        int next = tile + gridDim.x;
        if (next < N_TILES) stage(next, buf ^ 1);

        float C[2][4][4];
        #pragma unroll
        for (int mt = 0; mt < 2; mt++)
            #pragma unroll
            for (int nt = 0; nt < 4; nt++)
                #pragma unroll
                for (int i = 0; i < 4; i++) C[mt][nt][i] = 0.f;

        const uint32_t aBase = sA + buf * A_BUF + aOff;
        #pragma unroll
        for (int k = 0; k < 16; k++) {    // 16 k-steps of 16 halves
            uint32_t a0[4], a1[4], b0[4], b1[4];
            LDSM4(a0, aBase + k * 32);
            LDSM4(a1, aBase + 16 * RSTRIDE + k * 32);
            LDSM4(b0, bAddr0 + k * 32);
            LDSM4(b1, bAddr0 + 16 * RSTRIDE + k * 32);
            mma_f16(C[0][0], a0, b0);
            mma_f16(C[0][1], a0, b0 + 2);
            mma_f16(C[0][2], a0, b1);
            mma_f16(C[0][3], a0, b1 + 2);
            mma_f16(C[1][0], a1, b0);
            mma_f16(C[1][1], a1, b0 + 2);
            mma_f16(C[1][2], a1, b1);
            mma_f16(C[1][3], a1, b1 + 2);
        }
        __syncthreads();                  // all warps done reading buf

        // --- epilogue: h = relu(c + bn); p += h * fc; quad-reduce ----------
        float p[2][2][2];   // [mt][rowhalf][cls]
        #pragma unroll
        for (int mt = 0; mt < 2; mt++)
            #pragma unroll
            for (int hh = 0; hh < 2; hh++) { p[mt][hh][0] = 0.f; p[mt][hh][1] = 0.f; }

        #pragma unroll
        for (int nt = 0; nt < 4; nt++) {
            #pragma unroll
            for (int ii = 0; ii < 2; ii++) {
                int col = n_idx * 32 + nt * 8 + 2 * tcol + ii;
                float bnv = bn_s[col], f0v = f0_s[col], f1v = f1_s[col];
                #pragma unroll
                for (int mt = 0; mt < 2; mt++) {
                    #pragma unroll
                    for (int hh = 0; hh < 2; hh++) {
                        float h = fmaxf(C[mt][nt][hh * 2 + ii] + bnv, 0.f);
                        p[mt][hh][0] += h * f0v;
                        p[mt][hh][1] += h * f1v;
                    }
                }
            }
        }
        #pragma unroll
        for (int mt = 0; mt < 2; mt++)
            #pragma unroll
            for (int hh = 0; hh < 2; hh++)
                #pragma unroll
                for (int cl = 0; cl < 2; cl++) {
                    float v = p[mt][hh][cl];
                    v += __shfl_xor_sync(0xffffffffu, v, 1);
                    v += __shfl_xor_sync(0xffffffffu, v, 2);
                    p[mt][hh][cl] = v;
                }
        if (tcol == 0) {
            #pragma unroll
            for (int mt = 0; mt < 2; mt++)
                #pragma unroll
                for (int hh = 0; hh < 2; hh++) {
                    int row = m_idx * 32 + mt * 16 + hh * 8 + groupr;
                    part[row * 8 + n_idx * 2 + 0] = p[mt][hh][0];
                    part[row * 8 + n_idx * 2 + 1] = p[mt][hh][1];
                }
        }
        __syncthreads();
        if (tid < 128) {
            int node = tile * 128 + tid;
            if (node < N_NODES) {
                float l0 = part[tid * 8 + 0] + part[tid * 8 + 2] +
                           part[tid * 8 + 4] + part[tid * 8 + 6] + bfc0;
                float l1 = part[tid * 8 + 1] + part[tid * 8 + 3] +
                           part[tid * 8 + 5] + part[tid * 8 + 7] + bfc1;
                float2 o;
                o.x = 1.0f / (1.0f + expf(-l0));
                o.y = 1.0f / (1.0f + expf(-l1));
                *(float2*)&out[(size_t)node * 2] = o;
            }
        }
        buf ^= 1;
        // next tile's top-of-loop __syncthreads orders part/buf reuse
    }
}

// ---------------------------------------------------------------------------
extern "C" void kernel_launch(void* const* d_in, const int* in_sizes, int n_in,
                              void* d_out, int out_size) {
    const float* feat   = (const float*)d_in[0];
    const void*  src    = d_in[1];
    const void*  dst    = d_in[2];
    const float* Wself  = (const float*)d_in[3];
    const float* Wneigh = (const float*)d_in[4];
    const float* bneigh = (const float*)d_in[5];
    const float* Wfc    = (const float*)d_in[6];
    const float* bfc    = (const float*)d_in[7];
    float*       out    = (float*)d_out;
    int E = in_sizes[1];

    cudaFuncSetAttribute(mma_gemm_kernel,
                         cudaFuncAttributeMaxDynamicSharedMemorySize, SMEM_TOTAL);

    prep_fill_kernel<<<TOTAL_BLOCKS, 256>>>(feat, src, dst, E);
    aggregate_kernel<<<(N_NODES * 32 + 255) / 256, 256>>>();
    mma_gemm_kernel<<<148, 512, SMEM_TOTAL>>>(
        Wself, Wneigh, bneigh, Wfc, bfc, out);
}

// round 16
// speedup vs baseline: 1.8793x; 1.0159x over previous
#include <cuda_runtime.h>
#include <cuda_fp16.h>
#include <math.h>
#include <cstdint>

#define N_NODES 50000
#define F       128
#define NCLS    2
#define N_TILES ((N_NODES + 127) / 128)   // 391
#define BUCKET  64                         // slots per node (Poisson(16) safe)
#define PF_BLOCKS 1184                     // 8 CTAs/SM, one full wave

// Scratch (device globals: allocation-free; zero-initialized at load)
__device__ __half g_feat16[N_NODES * F];          // 12.8 MB
__device__ __half g_agg16[N_NODES * F];           // 12.8 MB (mean, scaled)
__device__ int    g_cnt[N_NODES];                 // zeroed by aggregate tail
__device__ int    g_bucket[N_NODES * BUCKET];     // 12.8 MB

// ---------------------------------------------------------------------------
// 0) prep+fill: edge fill FIRST at max parallelism (latency-bound phase),
//    then feat->fp16 conversion (BW-bound, insensitive to ordering)
// ---------------------------------------------------------------------------
__global__ void __launch_bounds__(256)
prep_fill_kernel(const float* __restrict__ feat,
                 const void* __restrict__ srcv,
                 const void* __restrict__ dstv, int E) {
    __shared__ int s_nz;
    int tid = threadIdx.x;
    if (tid == 0) s_nz = 0;
    __syncthreads();
    if (tid < 64) {                        // per-block dtype probe (L2-cached)
        const int* s32 = (const int*)srcv;
        const int* d32 = (const int*)dstv;
        int lim = 2 * E < 128 ? 2 * E : 128;
        int i = 2 * tid + 1;
        if (i < lim && (s32[i] | d32[i])) atomicOr(&s_nz, 1);
    }
    __syncthreads();
    const int is64 = (s_nz == 0);          // all odd 32b words zero => int64

    int gtid = blockIdx.x * 256 + tid;
    int stride = PF_BLOCKS * 256;          // 303,104 threads

    // edge fill: count + bucket append (max thread count, ~2.6 edges/thread)
    for (int i = gtid; i < E; i += stride) {
        int d, s;
        if (is64) {
            d = (int)reinterpret_cast<const long long*>(dstv)[i];
            s = (int)reinterpret_cast<const long long*>(srcv)[i];
        } else {
            d = reinterpret_cast<const int*>(dstv)[i];
            s = reinterpret_cast<const int*>(srcv)[i];
        }
        if (d < 0 || d >= N_NODES || s < 0 || s >= N_NODES) continue;
        int pos = atomicAdd(&g_cnt[d], 1);
        if (pos < BUCKET) g_bucket[(size_t)d * BUCKET + pos] = s;
    }

    // feat -> fp16 conversion
    const int NH4 = N_NODES * F / 4;
    const float4* f4 = (const float4*)feat;
    uint2* o2 = (uint2*)g_feat16;
    for (int i = gtid; i < NH4; i += stride) {
        float4 v = f4[i];
        __half2 h0 = __float22half2_rn(make_float2(v.x, v.y));
        __half2 h1 = __float22half2_rn(make_float2(v.z, v.w));
        uint2 o;
        o.x = *(uint32_t*)&h0;
        o.y = *(uint32_t*)&h1;
        o2[i] = o;
    }
}

// ---------------------------------------------------------------------------
// 1) aggregate: warp per node, fp16 gather, f32 accumulate, fp16 store;
//    zeroes g_cnt afterwards (invariant for next launch/graph replay)
// ---------------------------------------------------------------------------
__global__ void __launch_bounds__(256)
aggregate_kernel() {
    int warp = (blockIdx.x * blockDim.x + threadIdx.x) >> 5;
    int lane = threadIdx.x & 31;
    if (warp >= N_NODES) return;
    int deg = g_cnt[warp];
    int n = deg < BUCKET ? deg : BUCKET;
    const int* bk = &g_bucket[(size_t)warp * BUCKET];

    const uint2* f2 = (const uint2*)g_feat16;   // 32 uint2 per row (4 halves)
    float a0 = 0.f, a1 = 0.f, a2 = 0.f, a3 = 0.f;
    int e = 0;
    for (; e + 1 < n; e += 2) {
        int s0 = bk[e], s1 = bk[e + 1];
        uint2 u0 = f2[(size_t)s0 * 32 + lane];
        uint2 u1 = f2[(size_t)s1 * 32 + lane];
        float2 p0 = __half22float2(*(__half2*)&u0.x);
        float2 p1 = __half22float2(*(__half2*)&u0.y);
        float2 q0 = __half22float2(*(__half2*)&u1.x);
        float2 q1 = __half22float2(*(__half2*)&u1.y);
        a0 += p0.x + q0.x; a1 += p0.y + q0.y;
        a2 += p1.x + q1.x; a3 += p1.y + q1.y;
    }
    if (e < n) {
        int s0 = bk[e];
        uint2 u0 = f2[(size_t)s0 * 32 + lane];
        float2 p0 = __half22float2(*(__half2*)&u0.x);
        float2 p1 = __half22float2(*(__half2*)&u0.y);
        a0 += p0.x; a1 += p0.y; a2 += p1.x; a3 += p1.y;
    }
    float invd = __fdividef(1.0f, fmaxf((float)deg, 1.0f));
    __half2 h0 = __float22half2_rn(make_float2(a0 * invd, a1 * invd));
    __half2 h1 = __float22half2_rn(make_float2(a2 * invd, a3 * invd));
    uint2 o;
    o.x = *(uint32_t*)&h0;
    o.y = *(uint32_t*)&h1;
    ((uint2*)g_agg16)[(size_t)warp * 32 + lane] = o;
    if (lane == 0) g_cnt[warp] = 0;       // restore invariant for next call
}

// ---------------------------------------------------------------------------
// 2) fp16 mma GEMM: ldmatrix fragments with 2-stage k-pipeline, top-of-tile
//    cp.async prefetch, fused bias/relu/fc/sigmoid epilogue
// ---------------------------------------------------------------------------
#define RSTRIDE  528    // bytes per smem row (256 halves + 16B pad)
#define RWORDS   132    // u32 per row
#define A_BUF    67584  // 128 rows * 528 B
#define OFF_B    0
#define OFF_A    67584                    // 2 bufs -> 135168
#define OFF_BN   202752
#define OFF_F0   203264
#define OFF_F1   203776
#define OFF_PART 204288                   // [128][4][2] f32 = 4096 B
#define SMEM_TOTAL 208384

__device__ __forceinline__ uint32_t smem_u32(const void* p) {
    uint32_t a;
    asm("{ .reg .u64 t; cvta.to.shared.u64 t, %1; cvt.u32.u64 %0, t; }"
        : "=r"(a) : "l"(p));
    return a;
}
__device__ __forceinline__ void mma_f16(float* c, const uint32_t* a,
                                        const uint32_t* b) {
    asm volatile("mma.sync.aligned.m16n8k16.row.col.f32.f16.f16.f32 "
                 "{%0,%1,%2,%3}, {%4,%5,%6,%7}, {%8,%9}, {%0,%1,%2,%3};"
                 : "+f"(c[0]), "+f"(c[1]), "+f"(c[2]), "+f"(c[3])
                 : "r"(a[0]), "r"(a[1]), "r"(a[2]), "r"(a[3]),
                   "r"(b[0]), "r"(b[1]));
}
#define LDSM4(r, addr) \
    asm volatile("ldmatrix.sync.aligned.m8n8.x4.shared.b16 {%0,%1,%2,%3}, [%4];" \
                 : "=r"((r)[0]), "=r"((r)[1]), "=r"((r)[2]), "=r"((r)[3]) \
                 : "r"(addr))
#define CP_ASYNC16(dst, src) \
    asm volatile("cp.async.cg.shared.global [%0], [%1], 16;" \
                 :: "r"(dst), "l"(src) : "memory")
#define CP_COMMIT() asm volatile("cp.async.commit_group;" ::: "memory")
#define CP_WAIT0()  asm volatile("cp.async.wait_group 0;" ::: "memory")

__global__ void __launch_bounds__(512, 1)
mma_gemm_kernel(const float* __restrict__ Wself,
                const float* __restrict__ Wneigh,
                const float* __restrict__ bneigh,
                const float* __restrict__ Wfc,
                const float* __restrict__ bfc,
                float* __restrict__ out) {
    extern __shared__ char smem[];
    uint32_t* Bs = (uint32_t*)(smem + OFF_B);    // [n=128][k2=128]+pad
    float* bn_s  = (float*)(smem + OFF_BN);
    float* f0_s  = (float*)(smem + OFF_F0);
    float* f1_s  = (float*)(smem + OFF_F1);
    float* part  = (float*)(smem + OFF_PART);
    const uint32_t sbase = smem_u32(smem);
    const uint32_t sA = sbase + OFF_A;
    const uint32_t sB = sbase + OFF_B;

    const int tid = threadIdx.x;
    const int wid = tid >> 5, lane = tid & 31;
    const int m_idx = wid >> 2;          // 0..3: rows m_idx*32..+32
    const int n_idx = wid & 3;           // 0..3: cols n_idx*32..+32
    const int groupr = lane >> 2, tcol = lane & 3;

    // --- stage B = [Ws | Wn] as [n][k] fp16, once per CTA -------------------
    const float4* Ws4 = (const float4*)Wself;
    const float4* Wn4 = (const float4*)Wneigh;
    for (int t = tid; t < 128 * 64; t += 512) {
        int j  = t >> 6;                  // output col n (row of B)
        int kq = t & 63;                  // float4 index along combined K(256)
        float4 v = (kq < 32) ? Ws4[j * 32 + kq] : Wn4[j * 32 + (kq - 32)];
        __half2 h0 = __float22half2_rn(make_float2(v.x, v.y));
        __half2 h1 = __float22half2_rn(make_float2(v.z, v.w));
        uint2 o;
        o.x = *(uint32_t*)&h0;
        o.y = *(uint32_t*)&h1;
        *(uint2*)&Bs[j * RWORDS + kq * 2] = o;
    }
    if (tid < 128) {
        bn_s[tid] = bneigh[tid];
        f0_s[tid] = Wfc[tid];
        f1_s[tid] = Wfc[128 + tid];
    }

    const char* featb = (const char*)g_feat16;
    const char* aggb  = (const char*)g_agg16;
    const float bfc0 = bfc[0], bfc1 = bfc[1];

    // ldmatrix lane address components (bytes)
    const uint32_t aOff = (uint32_t)((m_idx * 32 + (lane & 15)) * RSTRIDE +
                                     (lane >> 4) * 16);
    const uint32_t bAddr0 = sB + (uint32_t)((n_idx * 32 + (lane & 7) +
                                             ((lane >> 4) & 1) * 8) * RSTRIDE +
                                            ((lane >> 3) & 1) * 16);

    // whole-tile A stager: 128 rows x 512 B (feat | agg), one commit group
    auto stage = [&](int tile, int bufi) {
        #pragma unroll
        for (int i = 0; i < 8; i++) {
            int idx = tid + i * 512;              // 0..4095
            int row = idx >> 5, q = idx & 31;     // 32 x 16B segs per row
            int node = tile * 128 + row;
            if (node >= N_NODES) node = N_NODES - 1;
            const char* src = (q < 16)
                ? featb + (size_t)node * 256 + q * 16
                : aggb  + (size_t)node * 256 + (q - 16) * 16;
            uint32_t dst = sA + bufi * A_BUF + row * RSTRIDE + q * 16;
            CP_ASYNC16(dst, src);
        }
        CP_COMMIT();
    };

    int buf = 0;
    int tile0 = blockIdx.x;
    if (tile0 < N_TILES) stage(tile0, 0);

    for (int tile = tile0; tile < N_TILES; tile += gridDim.x) {
        CP_WAIT0();
        __syncthreads();                  // A tile (buf) ready for all warps

        // prefetch NEXT tile now: copy overlaps the whole MMA + epilogue.
        int next = tile + gridDim.x;
        if (next < N_TILES) stage(next, buf ^ 1);

        float C[2][4][4];
        #pragma unroll
        for (int mt = 0; mt < 2; mt++)
            #pragma unroll
            for (int nt = 0; nt < 4; nt++)
                #pragma unroll
                for (int i = 0; i < 4; i++) C[mt][nt][i] = 0.f;

        const uint32_t aBase = sA + buf * A_BUF + aOff;

        // 2-stage software pipeline over the 16 k-steps
        uint32_t a0[2][4], a1[2][4], b0[2][4], b1[2][4];
        LDSM4(a0[0], aBase);
        LDSM4(a1[0], aBase + 16 * RSTRIDE);
        LDSM4(b0[0], bAddr0);
        LDSM4(b1[0], bAddr0 + 16 * RSTRIDE);
        #pragma unroll
        for (int k = 0; k < 16; k++) {
            int cur = k & 1, nxt = cur ^ 1;
            if (k < 15) {
                LDSM4(a0[nxt], aBase + (k + 1) * 32);
                LDSM4(a1[nxt], aBase + 16 * RSTRIDE + (k + 1) * 32);
                LDSM4(b0[nxt], bAddr0 + (k + 1) * 32);
                LDSM4(b1[nxt], bAddr0 + 16 * RSTRIDE + (k + 1) * 32);
            }
            mma_f16(C[0][0], a0[cur], b0[cur]);
            mma_f16(C[0][1], a0[cur], b0[cur] + 2);
            mma_f16(C[0][2], a0[cur], b1[cur]);
            mma_f16(C[0][3], a0[cur], b1[cur] + 2);
            mma_f16(C[1][0], a1[cur], b0[cur]);
            mma_f16(C[1][1], a1[cur], b0[cur] + 2);
            mma_f16(C[1][2], a1[cur], b1[cur]);
            mma_f16(C[1][3], a1[cur], b1[cur] + 2);
        }
        __syncthreads();                  // all warps done reading buf

        // --- epilogue: h = relu(c + bn); p += h * fc; quad-reduce ----------
        float p[2][2][2];   // [mt][rowhalf][cls]
        #pragma unroll
        for (int mt = 0; mt < 2; mt++)
            #pragma unroll
            for (int hh = 0; hh < 2; hh++) { p[mt][hh][0] = 0.f; p[mt][hh][1] = 0.f; }

        #pragma unroll
        for (int nt = 0; nt < 4; nt++) {
            #pragma unroll
            for (int ii = 0; ii < 2; ii++) {
                int col = n_idx * 32 + nt * 8 + 2 * tcol + ii;
                float bnv = bn_s[col], f0v = f0_s[col], f1v = f1_s[col];
                #pragma unroll
                for (int mt = 0; mt < 2; mt++) {
                    #pragma unroll
                    for (int hh = 0; hh < 2; hh++) {
                        float h = fmaxf(C[mt][nt][hh * 2 + ii] + bnv, 0.f);
                        p[mt][hh][0] += h * f0v;
                        p[mt][hh][1] += h * f1v;
                    }
                }
            }
        }
        #pragma unroll
        for (int mt = 0; mt < 2; mt++)
            #pragma unroll
            for (int hh = 0; hh < 2; hh++)
                #pragma unroll
                for (int cl = 0; cl < 2; cl++) {
                    float v = p[mt][hh][cl];
                    v += __shfl_xor_sync(0xffffffffu, v, 1);
                    v += __shfl_xor_sync(0xffffffffu, v, 2);
                    p[mt][hh][cl] = v;
                }
        if (tcol == 0) {
            #pragma unroll
            for (int mt = 0; mt < 2; mt++)
                #pragma unroll
                for (int hh = 0; hh < 2; hh++) {
                    int row = m_idx * 32 + mt * 16 + hh * 8 + groupr;
                    part[row * 8 + n_idx * 2 + 0] = p[mt][hh][0];
                    part[row * 8 + n_idx * 2 + 1] = p[mt][hh][1];
                }
        }
        __syncthreads();
        if (tid < 128) {
            int node = tile * 128 + tid;
            if (node < N_NODES) {
                float l0 = part[tid * 8 + 0] + part[tid * 8 + 2] +
                           part[tid * 8 + 4] + part[tid * 8 + 6] + bfc0;
                float l1 = part[tid * 8 + 1] + part[tid * 8 + 3] +
                           part[tid * 8 + 5] + part[tid * 8 + 7] + bfc1;
                float2 o;
                o.x = 1.0f / (1.0f + expf(-l0));
                o.y = 1.0f / (1.0f + expf(-l1));
                *(float2*)&out[(size_t)node * 2] = o;
            }
        }
        buf ^= 1;
        // next tile's top-of-loop __syncthreads orders part/buf reuse
    }
}

// ---------------------------------------------------------------------------
extern "C" void kernel_launch(void* const* d_in, const int* in_sizes, int n_in,
                              void* d_out, int out_size) {
    const float* feat   = (const float*)d_in[0];
    const void*  src    = d_in[1];
    const void*  dst    = d_in[2];
    const float* Wself  = (const float*)d_in[3];
    const float* Wneigh = (const float*)d_in[4];
    const float* bneigh = (const float*)d_in[5];
    const float* Wfc    = (const float*)d_in[6];
    const float* bfc    = (const float*)d_in[7];
    float*       out    = (float*)d_out;
    int E = in_sizes[1];

    cudaFuncSetAttribute(mma_gemm_kernel,
                         cudaFuncAttributeMaxDynamicSharedMemorySize, SMEM_TOTAL);

    prep_fill_kernel<<<PF_BLOCKS, 256>>>(feat, src, dst, E);
    aggregate_kernel<<<(N_NODES * 32 + 255) / 256, 256>>>();
    mma_gemm_kernel<<<148, 512, SMEM_TOTAL>>>(
        Wself, Wneigh, bneigh, Wfc, bfc, out);
}